// round 2
// baseline (speedup 1.0000x reference)
#include <cuda_runtime.h>
#include <cstdint>

typedef unsigned long long u64;

// ---- packed f32x2 math (Blackwell sm_10x; ptxas never auto-generates these) ----
__device__ __forceinline__ u64 f2mul(u64 a, u64 b) {
    u64 d; asm("mul.rn.f32x2 %0, %1, %2;" : "=l"(d) : "l"(a), "l"(b)); return d;
}
__device__ __forceinline__ u64 f2add(u64 a, u64 b) {
    u64 d; asm("add.rn.f32x2 %0, %1, %2;" : "=l"(d) : "l"(a), "l"(b)); return d;
}
__device__ __forceinline__ u64 f2fma(u64 a, u64 b, u64 c) {
    u64 d; asm("fma.rn.f32x2 %0, %1, %2, %3;" : "=l"(d) : "l"(a), "l"(b), "l"(c)); return d;
}
__device__ __forceinline__ u64 dup2(float f) {
    u64 d; asm("mov.b64 %0, {%1, %1};" : "=l"(d) : "f"(f)); return d;
}

// packed constants {v, v}
#define HALF2  0x3F0000003F000000ULL   // { 0.5,    0.5   }
#define N8TH2  0xBE000000BE000000ULL   // {-0.125, -0.125 }
#define QURT2  0x3E8000003E800000ULL   // { 0.25,   0.25  }
#define N16T2  0xBD800000BD800000ULL   // {-0.0625,-0.0625}

// mid-level MAJ with 2x-scaled carry: inputs A,B,C are 2x true values,
// output = 2*maj(A/2,B/2,C/2) = A*(1/2 - B*C/8) + (B+C)/2
__device__ __forceinline__ u64 maj_scaled(u64 A, u64 B, u64 C) {
    u64 t = f2mul(B, C);
    u64 u = f2fma(t, N8TH2, HALF2);
    u64 s = f2add(B, C);
    u64 v = f2mul(s, HALF2);
    return f2fma(A, u, v);
}
// top-level: same, with the final /2 folded into the constants
__device__ __forceinline__ u64 maj_final(u64 A, u64 B, u64 C) {
    u64 t = f2mul(B, C);
    u64 u = f2fma(t, N16T2, QURT2);
    u64 s = f2add(B, C);
    u64 v = f2mul(s, QURT2);
    return f2fma(A, u, v);
}

// x: [8,3,64,64]  weight: [64,3,3,3]  out: [8,64,64,64]
// Block = 256 threads = 64 w-lanes x 4 co-slots. Grid = (64 rows, 4 batch
// pairs, 2 co-halves); each co-slot loops 8 output channels (stride 4).
// Each lane packs batch images (n0, n0+1) into one f32x2.
__global__ void __launch_bounds__(256, 2)
sconv_maj_kernel(const float* __restrict__ x,
                 const float* __restrict__ wgt,
                 float* __restrict__ out)
{
    __shared__ float2 sP[3][3][66];     // [ch][row][col+1], batch-pair interleaved
    __shared__ u64 sW4[64][9][4];       // per (co, triple): {W0, W1, W2, -(W0*W1*W2)} dup'd

    const int tid = threadIdx.x;
    const int h   = blockIdx.x;          // output row
    const int n0  = blockIdx.y * 2;      // batch pair
    const int z   = blockIdx.z;          // co half

    // ---- stage input strip (rows h-1..h+1, cols -1..64, 3 ch, 2 batches) ----
    for (int idx = tid; idx < 3 * 3 * 66; idx += 256) {
        int c   = idx / 198;
        int rem = idx - c * 198;
        int r   = rem / 66;
        int col = rem - r * 66;
        int hh  = h - 1 + r;
        int ww  = col - 1;
        float2 v = make_float2(0.f, 0.f);
        if (hh >= 0 && hh < 64 && ww >= 0 && ww < 64) {
            int off = (c * 64 + hh) * 64 + ww;
            v.x = x[n0 * 12288 + off];
            v.y = x[n0 * 12288 + 12288 + off];
        }
        sP[c][r][col] = v;
    }
    // ---- precomputed weight table: {W0, W1, W2, -(W0W1W2)} per (co, triple) ----
    for (int idx = tid; idx < 64 * 9; idx += 256) {
        int co = idx / 9, q = idx % 9;
        float w0 = wgt[co * 27 + q * 3 + 0];
        float w1 = wgt[co * 27 + q * 3 + 1];
        float w2 = wgt[co * 27 + q * 3 + 2];
        sW4[co][q][0] = dup2(w0);
        sW4[co][q][1] = dup2(w1);
        sW4[co][q][2] = dup2(w2);
        sW4[co][q][3] = dup2(-(w0 * w1 * w2));
    }
    __syncthreads();

    const int w = tid & 63;    // pixel column
    const int g = tid >> 6;    // co slot 0..3

    // ---- 27 packed patches + 9 patch triple-products in registers ----
    const u64* Pb = reinterpret_cast<const u64*>(&sP[0][0][0]);
    u64 P[27], PP[9];
    #pragma unroll
    for (int q = 0; q < 9; ++q) {
        #pragma unroll
        for (int j = 0; j < 3; ++j)
            P[q * 3 + j] = Pb[q * 66 + w + j];
        PP[q] = f2mul(f2mul(P[q * 3], P[q * 3 + 1]), P[q * 3 + 2]);
    }

    int co = z * 32 + g;
    int ob = ((n0 * 64 + co) * 64 + h) * 64 + w;
    const ulonglong2* wv = reinterpret_cast<const ulonglong2*>(&sW4[co][0][0]);

    #pragma unroll 1
    for (int cc = 0; cc < 8; ++cc) {
        u64 m2[3];
        #pragma unroll
        for (int ch = 0; ch < 3; ++ch) {
            u64 l1[3];
            #pragma unroll
            for (int t3 = 0; t3 < 3; ++t3) {
                const int q = ch * 3 + t3;
                ulonglong2 wa = wv[2 * q];       // {W0, W1}
                ulonglong2 wb = wv[2 * q + 1];   // {W2, -(W0W1W2)}
                u64 s = f2mul(wb.x, P[q * 3 + 2]);
                s = f2fma(wa.y, P[q * 3 + 1], s);
                s = f2fma(wa.x, P[q * 3 + 0], s);
                l1[t3] = f2fma(wb.y, PP[q], s);  // = 2*maj of the triple
            }
            m2[ch] = maj_scaled(l1[0], l1[1], l1[2]);
        }
        u64 res = maj_final(m2[0], m2[1], m2[2]);

        float2 rf;
        asm("mov.b64 {%0, %1}, %2;" : "=f"(rf.x), "=f"(rf.y) : "l"(res));
        out[ob]          = rf.x;        // batch n0
        out[ob + 262144] = rf.y;        // batch n0+1

        ob += 4 * 4096;                 // co += 4
        wv += 4 * 18;                   // 18 ulonglong2 per co
    }
}

extern "C" void kernel_launch(void* const* d_in, const int* in_sizes, int n_in,
                              void* d_out, int out_size)
{
    const float* x   = (const float*)d_in[0];   // [8,3,64,64]
    const float* wgt = (const float*)d_in[1];   // [64,3,3,3]
    float* out = (float*)d_out;                 // [8,64,64,64]

    dim3 grid(64, 4, 2);
    sconv_maj_kernel<<<grid, 256>>>(x, wgt, out);
}

// round 3
// speedup vs baseline: 1.1572x; 1.1572x over previous
#include <cuda_runtime.h>
#include <cstdint>

typedef unsigned long long u64;

// ---- packed f32x2 math (Blackwell sm_10x; ptxas never auto-generates these) ----
__device__ __forceinline__ u64 f2mul(u64 a, u64 b) {
    u64 d; asm("mul.rn.f32x2 %0, %1, %2;" : "=l"(d) : "l"(a), "l"(b)); return d;
}
__device__ __forceinline__ u64 f2add(u64 a, u64 b) {
    u64 d; asm("add.rn.f32x2 %0, %1, %2;" : "=l"(d) : "l"(a), "l"(b)); return d;
}
__device__ __forceinline__ u64 f2fma(u64 a, u64 b, u64 c) {
    u64 d; asm("fma.rn.f32x2 %0, %1, %2, %3;" : "=l"(d) : "l"(a), "l"(b), "l"(c)); return d;
}
__device__ __forceinline__ u64 dup2(float f) {
    u64 d; asm("mov.b64 %0, {%1, %1};" : "=l"(d) : "f"(f)); return d;
}

// packed constants {v, v}
#define HALF2  0x3F0000003F000000ULL   // { 0.5,    0.5   }
#define N8TH2  0xBE000000BE000000ULL   // {-0.125, -0.125 }
#define QURT2  0x3E8000003E800000ULL   // { 0.25,   0.25  }
#define N16T2  0xBD800000BD800000ULL   // {-0.0625,-0.0625}

// mid-level MAJ, 2x-scaled carry: out = 2*maj(A/2,B/2,C/2) = A*(1/2 - BC/8) + (B+C)/2
__device__ __forceinline__ u64 maj_scaled(u64 A, u64 B, u64 C) {
    u64 t = f2mul(B, C);
    u64 u = f2fma(t, N8TH2, HALF2);
    u64 s = f2add(B, C);
    u64 v = f2mul(s, HALF2);
    return f2fma(A, u, v);
}
// top-level: final /2 folded into the constants
__device__ __forceinline__ u64 maj_final(u64 A, u64 B, u64 C) {
    u64 t = f2mul(B, C);
    u64 u = f2fma(t, N16T2, QURT2);
    u64 s = f2add(B, C);
    u64 v = f2mul(s, QURT2);
    return f2fma(A, u, v);
}

// level-1 core given weights {W0,W1} {W2,Wp=-(W0W1W2)} and patches P0..P2, PP=P0P1P2:
//   2*maj = W0P0 + W1P1 + W2P2 + Wp*PP
__device__ __forceinline__ u64 lvl1(ulonglong2 wa, ulonglong2 wb,
                                    u64 P0, u64 P1, u64 P2, u64 PP) {
    u64 s = f2mul(wb.x, P2);
    s = f2fma(wa.y, P1, s);
    s = f2fma(wa.x, P0, s);
    return f2fma(wb.y, PP, s);
}

// x: [8,3,64,64]  weight: [64,3,3,3]  out: [8,64,64,64]
// Block = 128 threads = 64 w-lanes x 2 co-slots; each thread computes TWO
// vertically-adjacent output rows (h0, h0+1), batch-pair packed in f32x2,
// looping 8 output channels. Grid = (32 row-pairs, 4 batch-pairs, 4 co-quarters).
__global__ void __launch_bounds__(128, 4)
sconv_maj_kernel(const float* __restrict__ x,
                 const float* __restrict__ wgt,
                 float* __restrict__ out)
{
    __shared__ float2 sP[3][4][66];     // [ch][imgrow h0-1..h0+2][col+1], batch-interleaved
    __shared__ u64 sW4[16][9][4];       // per (co_local, triple): {W0,W1,W2,-(W0W1W2)} dup'd

    const int tid = threadIdx.x;
    const int h0  = blockIdx.x * 2;      // first output row of the pair
    const int n0  = blockIdx.y * 2;      // batch pair
    const int z   = blockIdx.z;          // co quarter (16 channels)

    // ---- stage input strip (rows h0-1..h0+2, cols -1..64, 3 ch, 2 batches) ----
    for (int idx = tid; idx < 3 * 4 * 66; idx += 128) {
        int c   = idx / 264;
        int rem = idx - c * 264;
        int r   = rem / 66;
        int col = rem - r * 66;
        int hh  = h0 - 1 + r;
        int ww  = col - 1;
        float2 v = make_float2(0.f, 0.f);
        if (hh >= 0 && hh < 64 && ww >= 0 && ww < 64) {
            int off = (c * 64 + hh) * 64 + ww;
            v.x = x[n0 * 12288 + off];
            v.y = x[n0 * 12288 + 12288 + off];
        }
        sP[c][r][col] = v;
    }
    // ---- weight table for this co quarter: {W0,W1,W2,-(W0W1W2)} dup'd ----
    for (int idx = tid; idx < 16 * 9; idx += 128) {
        int col = idx / 9, q = idx % 9;
        const float* wp = wgt + (z * 16 + col) * 27 + q * 3;
        float w0 = wp[0], w1 = wp[1], w2 = wp[2];
        sW4[col][q][0] = dup2(w0);
        sW4[col][q][1] = dup2(w1);
        sW4[col][q][2] = dup2(w2);
        sW4[col][q][3] = dup2(-(w0 * w1 * w2));
    }
    __syncthreads();

    const int w = tid & 63;    // pixel column
    const int g = tid >> 6;    // co slot (0..1)

    // ---- register-cache 36 packed patches (3ch x 4rows x 3cols) + 12 row-products ----
    const u64* Pb = reinterpret_cast<const u64*>(&sP[0][0][0]);
    u64 P[3][4][3], PP[3][4];
    #pragma unroll
    for (int c = 0; c < 3; ++c)
        #pragma unroll
        for (int r = 0; r < 4; ++r) {
            #pragma unroll
            for (int j = 0; j < 3; ++j)
                P[c][r][j] = Pb[(c * 4 + r) * 66 + w + j];
            PP[c][r] = f2mul(f2mul(P[c][r][0], P[c][r][1]), P[c][r][2]);
        }

    const int co0 = z * 16 + g;
    int ob = ((n0 * 64 + co0) * 64 + h0) * 64 + w;
    const ulonglong2* wv = reinterpret_cast<const ulonglong2*>(&sW4[g][0][0]);

    #pragma unroll 2
    for (int cc = 0; cc < 8; ++cc) {
        u64 m2a[3], m2b[3];              // level-2 results for the two output rows
        #pragma unroll
        for (int c = 0; c < 3; ++c) {
            u64 l1a[3], l1b[3];
            #pragma unroll
            for (int kr = 0; kr < 3; ++kr) {
                const int q = c * 3 + kr;
                ulonglong2 wa = wv[2 * q];       // {W0, W1}
                ulonglong2 wb = wv[2 * q + 1];   // {W2, -(W0W1W2)}
                l1a[kr] = lvl1(wa, wb, P[c][kr  ][0], P[c][kr  ][1], P[c][kr  ][2], PP[c][kr  ]);
                l1b[kr] = lvl1(wa, wb, P[c][kr+1][0], P[c][kr+1][1], P[c][kr+1][2], PP[c][kr+1]);
            }
            m2a[c] = maj_scaled(l1a[0], l1a[1], l1a[2]);
            m2b[c] = maj_scaled(l1b[0], l1b[1], l1b[2]);
        }
        u64 ra = maj_final(m2a[0], m2a[1], m2a[2]);
        u64 rb = maj_final(m2b[0], m2b[1], m2b[2]);

        float2 fa, fb;
        asm("mov.b64 {%0, %1}, %2;" : "=f"(fa.x), "=f"(fa.y) : "l"(ra));
        asm("mov.b64 {%0, %1}, %2;" : "=f"(fb.x), "=f"(fb.y) : "l"(rb));
        out[ob]               = fa.x;    // batch n0,   row h0
        out[ob + 64]          = fb.x;    // batch n0,   row h0+1
        out[ob + 262144]      = fa.y;    // batch n0+1, row h0
        out[ob + 262144 + 64] = fb.y;    // batch n0+1, row h0+1

        ob += 2 * 4096;                  // co += 2
        wv += 2 * 18;                    // 18 ulonglong2 per co
    }
}

extern "C" void kernel_launch(void* const* d_in, const int* in_sizes, int n_in,
                              void* d_out, int out_size)
{
    const float* x   = (const float*)d_in[0];   // [8,3,64,64]
    const float* wgt = (const float*)d_in[1];   // [64,3,3,3]
    float* out = (float*)d_out;                 // [8,64,64,64]

    dim3 grid(32, 4, 4);   // 32 row-pairs x 4 batch-pairs x 4 co-quarters
    sconv_maj_kernel<<<grid, 128>>>(x, wgt, out);
}

// round 4
// speedup vs baseline: 1.2046x; 1.0409x over previous
#include <cuda_runtime.h>
#include <cstdint>

typedef unsigned long long u64;

// ---- packed f32x2 math (Blackwell sm_10x; ptxas never auto-generates these) ----
__device__ __forceinline__ u64 f2mul(u64 a, u64 b) {
    u64 d; asm("mul.rn.f32x2 %0, %1, %2;" : "=l"(d) : "l"(a), "l"(b)); return d;
}
__device__ __forceinline__ u64 f2add(u64 a, u64 b) {
    u64 d; asm("add.rn.f32x2 %0, %1, %2;" : "=l"(d) : "l"(a), "l"(b)); return d;
}
__device__ __forceinline__ u64 f2fma(u64 a, u64 b, u64 c) {
    u64 d; asm("fma.rn.f32x2 %0, %1, %2, %3;" : "=l"(d) : "l"(a), "l"(b), "l"(c)); return d;
}
__device__ __forceinline__ u64 dup2(float f) {
    u64 d; asm("mov.b64 %0, {%1, %1};" : "=l"(d) : "f"(f)); return d;
}

// packed constants {v, v}
#define HALF2  0x3F0000003F000000ULL   // { 0.5,    0.5   }
#define N8TH2  0xBE000000BE000000ULL   // {-0.125, -0.125 }
#define QURT2  0x3E8000003E800000ULL   // { 0.25,   0.25  }
#define N16T2  0xBD800000BD800000ULL   // {-0.0625,-0.0625}

// mid-level MAJ, 2x-scaled carry: out = 2*maj(A/2,B/2,C/2) = A*(1/2 - BC/8) + (B+C)/2
__device__ __forceinline__ u64 maj_scaled(u64 A, u64 B, u64 C) {
    u64 t = f2mul(B, C);
    u64 u = f2fma(t, N8TH2, HALF2);
    u64 s = f2add(B, C);
    u64 v = f2mul(s, HALF2);
    return f2fma(A, u, v);
}
// top-level: final /2 folded into the constants
__device__ __forceinline__ u64 maj_final(u64 A, u64 B, u64 C) {
    u64 t = f2mul(B, C);
    u64 u = f2fma(t, N16T2, QURT2);
    u64 s = f2add(B, C);
    u64 v = f2mul(s, QURT2);
    return f2fma(A, u, v);
}

// level-1: weights {W0,W1} {W2,Wp=-(W0W1W2)}, patches P0..P2, PP=P0P1P2:
//   2*maj = W0P0 + W1P1 + W2P2 + Wp*PP
__device__ __forceinline__ u64 lvl1(ulonglong2 wa, ulonglong2 wb,
                                    u64 P0, u64 P1, u64 P2, u64 PP) {
    u64 s = f2mul(wb.x, P2);
    s = f2fma(wa.y, P1, s);
    s = f2fma(wa.x, P0, s);
    return f2fma(wb.y, PP, s);
}

// x: [8,3,64,64]  weight: [64,3,3,3]  out: [8,64,64,64]
// Block = 128 threads = 64 w-lanes x 2 co-slots; each thread computes TWO
// vertically-adjacent output rows (h0, h0+1), batch-pair packed in f32x2,
// looping 4 output channels. Grid = (32 row-pairs, 4 batch-pairs, 8 co-eighths)
// = 1024 blocks -> 1.73 residency waves (4 blocks/SM reg-limited).
__global__ void __launch_bounds__(128, 4)
sconv_maj_kernel(const float* __restrict__ x,
                 const float* __restrict__ wgt,
                 float* __restrict__ out)
{
    __shared__ float2 sP[3][4][66];     // [ch][imgrow h0-1..h0+2][col+1], batch-interleaved
    __shared__ u64 sW4[8][9][4];        // per (co_local, triple): {W0,W1,W2,-(W0W1W2)} dup'd

    const int tid = threadIdx.x;
    const int h0  = blockIdx.x * 2;      // first output row of the pair
    const int n0  = blockIdx.y * 2;      // batch pair
    const int z   = blockIdx.z;          // co eighth (8 channels)

    // ---- stage input strip (rows h0-1..h0+2, cols -1..64, 3 ch, 2 batches) ----
    #pragma unroll
    for (int it = 0; it < 7; ++it) {
        int idx = tid + it * 128;
        if (idx < 3 * 4 * 66) {
            int c   = idx / 264;
            int rem = idx - c * 264;
            int r   = rem / 66;
            int col = rem - r * 66;
            int hh  = h0 - 1 + r;
            int ww  = col - 1;
            float2 v = make_float2(0.f, 0.f);
            if (hh >= 0 && hh < 64 && ww >= 0 && ww < 64) {
                int off = (c * 64 + hh) * 64 + ww;
                v.x = x[n0 * 12288 + off];
                v.y = x[n0 * 12288 + 12288 + off];
            }
            sP[c][r][col] = v;
        }
    }
    // ---- weight table for this co eighth: {W0,W1,W2,-(W0W1W2)} dup'd ----
    if (tid < 72) {
        int col = tid / 9, q = tid % 9;
        const float* wp = wgt + (z * 8 + col) * 27 + q * 3;
        float w0 = wp[0], w1 = wp[1], w2 = wp[2];
        sW4[col][q][0] = dup2(w0);
        sW4[col][q][1] = dup2(w1);
        sW4[col][q][2] = dup2(w2);
        sW4[col][q][3] = dup2(-(w0 * w1 * w2));
    }
    __syncthreads();

    const int w = tid & 63;    // pixel column
    const int g = tid >> 6;    // co slot (0..1)

    // ---- register-cache 36 packed patches (3ch x 4rows x 3cols) + 12 row-products ----
    const u64* Pb = reinterpret_cast<const u64*>(&sP[0][0][0]);
    u64 P[3][4][3], PP[3][4];
    #pragma unroll
    for (int c = 0; c < 3; ++c)
        #pragma unroll
        for (int r = 0; r < 4; ++r) {
            #pragma unroll
            for (int j = 0; j < 3; ++j)
                P[c][r][j] = Pb[(c * 4 + r) * 66 + w + j];
            PP[c][r] = f2mul(f2mul(P[c][r][0], P[c][r][1]), P[c][r][2]);
        }

    const int co0 = z * 8 + g;
    int ob = ((n0 * 64 + co0) * 64 + h0) * 64 + w;
    const ulonglong2* wv = reinterpret_cast<const ulonglong2*>(&sW4[g][0][0]);

    #pragma unroll 2
    for (int cc = 0; cc < 4; ++cc) {
        u64 m2a[3], m2b[3];              // level-2 results for the two output rows
        #pragma unroll
        for (int c = 0; c < 3; ++c) {
            u64 l1a[3], l1b[3];
            #pragma unroll
            for (int kr = 0; kr < 3; ++kr) {
                const int q = c * 3 + kr;
                ulonglong2 wa = wv[2 * q];       // {W0, W1}
                ulonglong2 wb = wv[2 * q + 1];   // {W2, -(W0W1W2)}
                l1a[kr] = lvl1(wa, wb, P[c][kr  ][0], P[c][kr  ][1], P[c][kr  ][2], PP[c][kr  ]);
                l1b[kr] = lvl1(wa, wb, P[c][kr+1][0], P[c][kr+1][1], P[c][kr+1][2], PP[c][kr+1]);
            }
            m2a[c] = maj_scaled(l1a[0], l1a[1], l1a[2]);
            m2b[c] = maj_scaled(l1b[0], l1b[1], l1b[2]);
        }
        u64 ra = maj_final(m2a[0], m2a[1], m2a[2]);
        u64 rb = maj_final(m2b[0], m2b[1], m2b[2]);

        float2 fa, fb;
        asm("mov.b64 {%0, %1}, %2;" : "=f"(fa.x), "=f"(fa.y) : "l"(ra));
        asm("mov.b64 {%0, %1}, %2;" : "=f"(fb.x), "=f"(fb.y) : "l"(rb));
        out[ob]               = fa.x;    // batch n0,   row h0
        out[ob + 64]          = fb.x;    // batch n0,   row h0+1
        out[ob + 262144]      = fa.y;    // batch n0+1, row h0
        out[ob + 262144 + 64] = fb.y;    // batch n0+1, row h0+1

        ob += 2 * 4096;                  // co += 2
        wv += 2 * 18;                    // 18 ulonglong2 per co
    }
}

extern "C" void kernel_launch(void* const* d_in, const int* in_sizes, int n_in,
                              void* d_out, int out_size)
{
    const float* x   = (const float*)d_in[0];   // [8,3,64,64]
    const float* wgt = (const float*)d_in[1];   // [64,3,3,3]
    float* out = (float*)d_out;                 // [8,64,64,64]

    dim3 grid(32, 4, 8);   // 32 row-pairs x 4 batch-pairs x 8 co-eighths
    sconv_maj_kernel<<<grid, 128>>>(x, wgt, out);
}